// round 3
// baseline (speedup 1.0000x reference)
#include <cuda_runtime.h>
#include <math.h>

// Problem constants (fixed by setup_inputs)
#define Bq 2
#define Lq 4096
#define Hq 8
#define Dq 64
#define Mq 128
#define Cq 64
#define NCq (Lq / Cq)      // 64 chunks
#define BHq (Bq * Hq)      // 16 sequences

#define RATIO 0.08838834764831845f   // 1/sqrt(128)
#define STAB  1e-3f

// ---------------- scratch (device globals; no runtime allocation) ----------
__device__ float g_qp[BHq * Lq * Mq];          // [bh, l, m]  32MB
__device__ float g_kp[BHq * Lq * Mq];          // [bh, l, m]  32MB
__device__ float g_kv[BHq * NCq * Mq * Dq];    // [bh, c, m, d] 32MB (becomes exclusive prefix)
__device__ float g_ks[BHq * NCq * Mq];         // [bh, c, m]  (becomes exclusive prefix)

// ---------------- float4 helpers ----------------
__device__ __forceinline__ float4 f4z() { return make_float4(0.f, 0.f, 0.f, 0.f); }
__device__ __forceinline__ void fma44(float4& a, float4 x, float4 y) {
    a.x = fmaf(x.x, y.x, a.x); a.y = fmaf(x.y, y.y, a.y);
    a.z = fmaf(x.z, y.z, a.z); a.w = fmaf(x.w, y.w, a.w);
}
__device__ __forceinline__ void fma41(float4& a, float s, float4 y) {
    a.x = fmaf(s, y.x, a.x); a.y = fmaf(s, y.y, a.y);
    a.z = fmaf(s, y.z, a.z); a.w = fmaf(s, y.w, a.w);
}
__device__ __forceinline__ void add4(float4& a, float4 b) {
    a.x += b.x; a.y += b.y; a.z += b.z; a.w += b.w;
}
__device__ __forceinline__ float hsum4(float4 a) { return (a.x + a.y) + (a.z + a.w); }

// ======================= Kernel 1: projection + relu =======================
// grid 2*BH*NC (first half -> qp, second -> kp), 256 threads
// smem: P as float4 [128][17] (pad), X rows float4 [64][16]
#define PROJ_SMEM ((128 * 17 + 64 * 16) * 16)
__global__ void proj_kernel(const float* __restrict__ Q,
                            const float* __restrict__ K,
                            const float* __restrict__ P) {
    extern __shared__ float4 sm4[];
    float4* Ps = sm4;              // 128 x 17
    float4* Xs = Ps + 128 * 17;    // 64 x 16

    int bid   = blockIdx.x;
    int which = (bid >= BHq * NCq) ? 1 : 0;
    int rid   = bid - which * (BHq * NCq);
    int bh = rid / NCq, c = rid % NCq;
    int b = bh / Hq, h = bh % Hq;
    const float* X = which ? K : Q;
    float* OUT = which ? g_kp : g_qp;
    int tid = threadIdx.x;
    int lbase = c * Cq;

    for (int i = tid; i < 128 * 16; i += 256) {
        int m = i >> 4, d4 = i & 15;
        Ps[m * 17 + d4] = reinterpret_cast<const float4*>(P)[m * 16 + d4];
    }
    for (int i = tid; i < 64 * 16; i += 256) {
        int l = i >> 4, d4 = i & 15;
        Xs[i] = reinterpret_cast<const float4*>(X)[((b * Lq + lbase + l) * Hq + h) * 16 + d4];
    }
    __syncthreads();

    // 2048 tiles (16 l-tiles x 128 m), 8 reps: 4 rows per thread
    for (int rep = 0; rep < 8; rep++) {
        int t  = rep * 256 + tid;
        int lt = t >> 7;       // 0..15
        int m  = t & 127;      // consecutive within warp -> conflict-free on Ps
        float4 a0 = f4z(), a1 = f4z(), a2 = f4z(), a3 = f4z();
#pragma unroll
        for (int d4 = 0; d4 < 16; d4++) {
            float4 p  = Ps[m * 17 + d4];
            fma44(a0, Xs[(lt * 4 + 0) * 16 + d4], p);
            fma44(a1, Xs[(lt * 4 + 1) * 16 + d4], p);
            fma44(a2, Xs[(lt * 4 + 2) * 16 + d4], p);
            fma44(a3, Xs[(lt * 4 + 3) * 16 + d4], p);
        }
        int rowbase = bh * Lq + lbase + lt * 4;
        OUT[(rowbase + 0) * Mq + m] = fmaxf(hsum4(a0) * RATIO, 0.f) + STAB;
        OUT[(rowbase + 1) * Mq + m] = fmaxf(hsum4(a1) * RATIO, 0.f) + STAB;
        OUT[(rowbase + 2) * Mq + m] = fmaxf(hsum4(a2) * RATIO, 0.f) + STAB;
        OUT[(rowbase + 3) * Mq + m] = fmaxf(hsum4(a3) * RATIO, 0.f) + STAB;
    }
}

// ======================= Kernel 2: per-chunk KV / ksum =======================
// grid BH*NC, 256 threads
// smem: kp float4 [64][33] (pad), v float4 [64][17]
#define CS_SMEM ((64 * 33 + 64 * 17) * 16)
__global__ void chunksum_kernel(const float* __restrict__ V) {
    extern __shared__ float4 sm4[];
    float4* kp4 = sm4;            // 64 x 33
    float4* v4  = kp4 + 64 * 33;  // 64 x 17
    float* kpf = reinterpret_cast<float*>(kp4);  // row stride 132 floats

    int bid = blockIdx.x;
    int bh = bid / NCq, c = bid % NCq;
    int b = bh / Hq, h = bh % Hq;
    int tid = threadIdx.x;
    int lbase = c * Cq;

    for (int i = tid; i < 64 * 32; i += 256) {
        int l = i >> 5, m4 = i & 31;
        kp4[l * 33 + m4] = reinterpret_cast<const float4*>(g_kp)[(bh * Lq + lbase + l) * 32 + m4];
    }
    for (int i = tid; i < 64 * 16; i += 256) {
        int l = i >> 4, d4 = i & 15;
        v4[l * 17 + d4] = reinterpret_cast<const float4*>(V)[((b * Lq + lbase + l) * Hq + h) * 16 + d4];
    }
    __syncthreads();

    int d4    = tid & 15;
    int mbase = (tid >> 4) * 8;       // 16 groups of 8 m-rows
    float4 acc[8];
#pragma unroll
    for (int j = 0; j < 8; j++) acc[j] = f4z();

    for (int l = 0; l < 64; l++) {
        float4 vv = v4[l * 17 + d4];
#pragma unroll
        for (int j = 0; j < 8; j++) {
            float kk = kpf[l * 132 + mbase + j];
            fma41(acc[j], kk, vv);
        }
    }
    int base = (bh * NCq + c) * Mq;
#pragma unroll
    for (int j = 0; j < 8; j++)
        reinterpret_cast<float4*>(g_kv)[(base + mbase + j) * 16 + d4] = acc[j];

    if (tid < 128) {
        float s = 0.f;
        for (int l = 0; l < 64; l++) s += kpf[l * 132 + tid];
        g_ks[base + tid] = s;
    }
}

// ======================= Kernel 3: exclusive prefix over chunks ==============
// grid BH*2 (2 slices per bh), 256 threads; each thread owns 4 float4 (16 floats)
__global__ void scan_kernel() {
    int bh    = blockIdx.x >> 1;
    int slice = blockIdx.x & 1;
    int tid   = threadIdx.x;
    int base4 = slice * 1024 + tid * 4;   // per-bh chunk = 2048 float4
    float4* kv4 = reinterpret_cast<float4*>(g_kv);

    float4 p0 = f4z(), p1 = f4z(), p2 = f4z(), p3 = f4z();
    for (int c = 0; c < NCq; c += 2) {
        int ia = (bh * NCq + c) * 2048 + base4;
        int ib = ia + 2048;
        float4 a0 = kv4[ia + 0], a1 = kv4[ia + 1], a2 = kv4[ia + 2], a3 = kv4[ia + 3];
        float4 b0 = kv4[ib + 0], b1 = kv4[ib + 1], b2 = kv4[ib + 2], b3 = kv4[ib + 3];
        kv4[ia + 0] = p0; kv4[ia + 1] = p1; kv4[ia + 2] = p2; kv4[ia + 3] = p3;
        add4(p0, a0); add4(p1, a1); add4(p2, a2); add4(p3, a3);
        kv4[ib + 0] = p0; kv4[ib + 1] = p1; kv4[ib + 2] = p2; kv4[ib + 3] = p3;
        add4(p0, b0); add4(p1, b1); add4(p2, b2); add4(p3, b3);
    }

    if (slice == 0 && tid < 128) {
        float pk = 0.f;
        for (int c = 0; c < NCq; c += 4) {
            int i0 = (bh * NCq + c) * Mq + tid;
            float a0 = g_ks[i0], a1 = g_ks[i0 + Mq], a2 = g_ks[i0 + 2 * Mq], a3 = g_ks[i0 + 3 * Mq];
            g_ks[i0]          = pk;
            g_ks[i0 + Mq]     = pk + a0;
            g_ks[i0 + 2 * Mq] = pk + a0 + a1;
            g_ks[i0 + 3 * Mq] = pk + a0 + a1 + a2;
            pk += a0 + a1 + a2 + a3;
        }
    }
}

// ======================= Kernel 4: per-chunk output ==========================
// grid BH*NC, 512 threads
// smem: qp[64][33]f4, kp[64][33]f4, v[64][17]f4, kv[128][17]f4, S[64][17]f4,
//       ksum[128]f, den[64]f
#define OUT_SMEM ((64 * 33 * 2 + 64 * 17 + 128 * 17 + 64 * 17) * 16 + (128 + 64) * 4)
__global__ void out_kernel(const float* __restrict__ V, float* __restrict__ OUT) {
    extern __shared__ float4 sm4[];
    float4* qp4 = sm4;                  // 64 x 33
    float4* kp4 = qp4 + 64 * 33;        // 64 x 33
    float4* v4  = kp4 + 64 * 33;        // 64 x 17
    float4* kv4 = v4 + 64 * 17;         // 128 x 17
    float4* S4  = kv4 + 128 * 17;       // 64 x 17
    float*  ks  = reinterpret_cast<float*>(S4 + 64 * 17);   // 128
    float*  den = ks + 128;                                  // 64
    float* qpf = reinterpret_cast<float*>(qp4);  // stride 132
    float* Sf  = reinterpret_cast<float*>(S4);   // stride 68

    int bid = blockIdx.x;
    int bh = bid / NCq, c = bid % NCq;
    int b = bh / Hq, h = bh % Hq;
    int tid = threadIdx.x;
    int lbase = c * Cq;

    for (int i = tid; i < 64 * 32; i += 512) {
        int l = i >> 5, m4 = i & 31;
        qp4[l * 33 + m4] = reinterpret_cast<const float4*>(g_qp)[(bh * Lq + lbase + l) * 32 + m4];
        kp4[l * 33 + m4] = reinterpret_cast<const float4*>(g_kp)[(bh * Lq + lbase + l) * 32 + m4];
    }
    for (int i = tid; i < 64 * 16; i += 512) {
        int l = i >> 4, d4 = i & 15;
        v4[l * 17 + d4] = reinterpret_cast<const float4*>(V)[((b * Lq + lbase + l) * Hq + h) * 16 + d4];
    }
    for (int i = tid; i < 128 * 16; i += 512) {
        int m = i >> 4, d4 = i & 15;
        kv4[m * 17 + d4] = reinterpret_cast<const float4*>(g_kv)[((bh * NCq + c) * Mq + m) * 16 + d4];
    }
    if (tid < 128) ks[tid] = g_ks[(bh * NCq + c) * Mq + tid];
    __syncthreads();

    // ---- S = qp @ kp^T (causal-masked, zeros stored above diagonal) ----
    for (int rep = 0; rep < 2; rep++) {
        int id = rep * 512 + tid;
        int lt = id >> 6;     // 0..15 (fixed per warp)
        int lp = id & 63;     // consecutive within warp
        int l0 = lt * 4;
        if (lp <= l0 + 3) {
            float4 a0 = f4z(), a1 = f4z(), a2 = f4z(), a3 = f4z();
#pragma unroll 8
            for (int m4 = 0; m4 < 32; m4++) {
                float4 kk = kp4[lp * 33 + m4];
                fma44(a0, qp4[(l0 + 0) * 33 + m4], kk);
                fma44(a1, qp4[(l0 + 1) * 33 + m4], kk);
                fma44(a2, qp4[(l0 + 2) * 33 + m4], kk);
                fma44(a3, qp4[(l0 + 3) * 33 + m4], kk);
            }
            Sf[(l0 + 0) * 68 + lp] = (lp <= l0 + 0) ? hsum4(a0) : 0.f;
            Sf[(l0 + 1) * 68 + lp] = (lp <= l0 + 1) ? hsum4(a1) : 0.f;
            Sf[(l0 + 2) * 68 + lp] = (lp <= l0 + 2) ? hsum4(a2) : 0.f;
            Sf[(l0 + 3) * 68 + lp] = hsum4(a3);
        } else {
            Sf[(l0 + 0) * 68 + lp] = 0.f;
            Sf[(l0 + 1) * 68 + lp] = 0.f;
            Sf[(l0 + 2) * 68 + lp] = 0.f;
            Sf[(l0 + 3) * 68 + lp] = 0.f;
        }
    }
    __syncthreads();

    // ---- denominator: row-sum of S + qp . ksum_prefix (8 lanes per row) ----
    {
        int l    = tid >> 3;        // 0..63
        int lane = tid & 7;         // 0..7
        float s = 0.f;
        for (int lp = lane; lp < 64; lp += 8) s += Sf[l * 68 + lp];
        for (int m = lane; m < Mq; m += 8)   s = fmaf(qpf[l * 132 + m], ks[m], s);
        s += __shfl_xor_sync(0xffffffffu, s, 4);
        s += __shfl_xor_sync(0xffffffffu, s, 2);
        s += __shfl_xor_sync(0xffffffffu, s, 1);
        if (lane == 0) den[l] = s;
    }
    __syncthreads();

    // ---- numerator: qp @ KV_prefix + S @ v ; divide; store ----
    int lt2 = tid >> 4;       // 0..31 (2 rows each)
    int d4  = tid & 15;
    int l0  = lt2 * 2;
    float4 a0 = f4z(), a1 = f4z();
#pragma unroll 4
    for (int m = 0; m < Mq; m++) {
        float4 kv = kv4[m * 17 + d4];
        fma41(a0, qpf[(l0 + 0) * 132 + m], kv);
        fma41(a1, qpf[(l0 + 1) * 132 + m], kv);
    }
    for (int lp = 0; lp <= l0 + 1; lp++) {
        float4 vv = v4[lp * 17 + d4];
        fma41(a0, Sf[(l0 + 0) * 68 + lp], vv);   // zero above diagonal
        fma41(a1, Sf[(l0 + 1) * 68 + lp], vv);
    }
    float id0 = 1.0f / den[l0];
    float id1 = 1.0f / den[l0 + 1];
    a0.x *= id0; a0.y *= id0; a0.z *= id0; a0.w *= id0;
    a1.x *= id1; a1.y *= id1; a1.z *= id1; a1.w *= id1;
    reinterpret_cast<float4*>(OUT)[((b * Lq + lbase + l0 + 0) * Hq + h) * 16 + d4] = a0;
    reinterpret_cast<float4*>(OUT)[((b * Lq + lbase + l0 + 1) * Hq + h) * 16 + d4] = a1;
}

// ============================ launch ============================
extern "C" void kernel_launch(void* const* d_in, const int* in_sizes, int n_in,
                              void* d_out, int out_size) {
    (void)in_sizes; (void)n_in; (void)out_size;
    const float* Q = (const float*)d_in[0];
    const float* K = (const float*)d_in[1];
    const float* V = (const float*)d_in[2];
    const float* P = (const float*)d_in[3];
    float* OUT = (float*)d_out;

    // Opt-in to >48KB dynamic smem (idempotent host calls; not stream ops)
    cudaFuncSetAttribute(proj_kernel,     cudaFuncAttributeMaxDynamicSharedMemorySize, PROJ_SMEM);
    cudaFuncSetAttribute(chunksum_kernel, cudaFuncAttributeMaxDynamicSharedMemorySize, CS_SMEM);
    cudaFuncSetAttribute(out_kernel,      cudaFuncAttributeMaxDynamicSharedMemorySize, OUT_SMEM);

    proj_kernel<<<2 * BHq * NCq, 256, PROJ_SMEM>>>(Q, K, P);
    chunksum_kernel<<<BHq * NCq, 256, CS_SMEM>>>(V);
    scan_kernel<<<BHq * 2, 256>>>();
    out_kernel<<<BHq * NCq, 512, OUT_SMEM>>>(V, OUT);
}

// round 5
// speedup vs baseline: 1.5009x; 1.5009x over previous
#include <cuda_runtime.h>
#include <stdint.h>
#include <math.h>

// Problem constants (fixed by setup_inputs)
#define Bq 2
#define Lq 4096
#define Hq 8
#define Dq 64
#define Mq 128
#define Cq 64
#define NCq (Lq / Cq)      // 64 chunks
#define BHq (Bq * Hq)      // 16 sequences

#define RATIO 0.08838834764831845f   // 1/sqrt(128)
#define STAB  1e-3f

// ---------------- scratch (device globals; no runtime allocation) ----------
__device__ float g_qp[BHq * Lq * Mq];          // [bh, l, m]
__device__ float g_kp[BHq * Lq * Mq];          // [bh, l, m]
__device__ float g_kv[BHq * NCq * Mq * Dq];    // [bh, c, m, d] -> exclusive prefix
__device__ float g_ks[BHq * NCq * Mq];         // [bh, c, m]   -> exclusive prefix

// ---------------- helpers ----------------
__device__ __forceinline__ float4 f4z() { return make_float4(0.f, 0.f, 0.f, 0.f); }
__device__ __forceinline__ void fma41(float4& a, float s, float4 y) {
    a.x = fmaf(s, y.x, a.x); a.y = fmaf(s, y.y, a.y);
    a.z = fmaf(s, y.z, a.z); a.w = fmaf(s, y.w, a.w);
}
__device__ __forceinline__ void add4(float4& a, float4 b) {
    a.x += b.x; a.y += b.y; a.z += b.z; a.w += b.w;
}

__device__ __forceinline__ uint32_t f2tf(float x) {
    uint32_t r; asm("cvt.rna.tf32.f32 %0, %1;" : "=r"(r) : "f"(x)); return r;
}
__device__ __forceinline__ uint4 cvt4(float4 v) {
    return make_uint4(f2tf(v.x), f2tf(v.y), f2tf(v.z), f2tf(v.w));
}
// m16n8k8 tf32 mma, fp32 accumulate (D = A*B + D)
__device__ __forceinline__ void mma8(float* c, uint32_t a0, uint32_t a1, uint32_t a2, uint32_t a3,
                                     uint32_t b0, uint32_t b1) {
    asm("mma.sync.aligned.m16n8k8.row.col.f32.tf32.tf32.f32 "
        "{%0,%1,%2,%3},{%4,%5,%6,%7},{%8,%9},{%0,%1,%2,%3};"
        : "+f"(c[0]), "+f"(c[1]), "+f"(c[2]), "+f"(c[3])
        : "r"(a0), "r"(a1), "r"(a2), "r"(a3), "r"(b0), "r"(b1));
}

// ======================= Kernel 1: projection + relu (TF32 MMA) =============
// grid 2*BH*NC, 256 threads (8 warps). Per block: X[64x64] @ P^T -> [64x128].
// smem (u32, stride 68 == 4 mod 32 -> conflict-free fragment loads):
//   Xs [64][68] tf32, Ps [128][68] tf32 (P rows are B col-major [n=m][k=d])
#define PROJ_SMEM ((64 * 68 + 128 * 68) * 4)
__global__ void proj_kernel(const float* __restrict__ Q,
                            const float* __restrict__ K,
                            const float* __restrict__ P) {
    extern __shared__ uint32_t sm[];
    uint32_t* Xs = sm;             // [64][68]
    uint32_t* Ps = sm + 64 * 68;   // [128][68]

    int bid   = blockIdx.x;
    int which = (bid >= BHq * NCq) ? 1 : 0;
    int rid   = bid - which * (BHq * NCq);
    int bh = rid / NCq, c = rid % NCq;
    int b = bh / Hq, h = bh % Hq;
    const float* X = which ? K : Q;
    float* OUT = which ? g_kp : g_qp;
    int tid = threadIdx.x;
    int lbase = c * Cq;

    for (int i = tid; i < 128 * 16; i += 256) {
        int m = i >> 4, d4 = i & 15;
        float4 v = reinterpret_cast<const float4*>(P)[m * 16 + d4];
        *reinterpret_cast<uint4*>(&Ps[m * 68 + d4 * 4]) = cvt4(v);
    }
    for (int i = tid; i < 64 * 16; i += 256) {
        int l = i >> 4, d4 = i & 15;
        float4 v = reinterpret_cast<const float4*>(X)[((b * Lq + lbase + l) * Hq + h) * 16 + d4];
        *reinterpret_cast<uint4*>(&Xs[l * 68 + d4 * 4]) = cvt4(v);
    }
    __syncthreads();

    int wid = tid >> 5, lane = tid & 31;
    int g = lane >> 2, t = lane & 3;
    int mt = wid & 3;    // m-tile (16 rows)
    int nh = wid >> 2;   // n-half (64 cols)
    int ar0 = (mt * 16 + g) * 68;
    int ar1 = ar0 + 8 * 68;

    float acc[8][4];
#pragma unroll
    for (int j = 0; j < 8; j++) { acc[j][0] = acc[j][1] = acc[j][2] = acc[j][3] = 0.f; }

#pragma unroll
    for (int k0 = 0; k0 < 64; k0 += 8) {
        uint32_t a0 = Xs[ar0 + k0 + t];
        uint32_t a1 = Xs[ar1 + k0 + t];
        uint32_t a2 = Xs[ar0 + k0 + t + 4];
        uint32_t a3 = Xs[ar1 + k0 + t + 4];
#pragma unroll
        for (int j = 0; j < 8; j++) {
            int n = nh * 64 + j * 8 + g;
            mma8(acc[j], a0, a1, a2, a3, Ps[n * 68 + k0 + t], Ps[n * 68 + k0 + t + 4]);
        }
    }

    int row0 = bh * Lq + lbase + mt * 16 + g;
#pragma unroll
    for (int j = 0; j < 8; j++) {
        int col = nh * 64 + j * 8 + 2 * t;
        float2 w0, w1;
        w0.x = fmaxf(acc[j][0] * RATIO, 0.f) + STAB;
        w0.y = fmaxf(acc[j][1] * RATIO, 0.f) + STAB;
        w1.x = fmaxf(acc[j][2] * RATIO, 0.f) + STAB;
        w1.y = fmaxf(acc[j][3] * RATIO, 0.f) + STAB;
        reinterpret_cast<float2*>(OUT)[(row0 * Mq + col) >> 1]          = w0;
        reinterpret_cast<float2*>(OUT)[((row0 + 8) * Mq + col) >> 1]    = w1;
    }
}

// ======================= Kernel 2: per-chunk KV / ksum (fp32) ===============
#define CS_SMEM ((64 * 33 + 64 * 17) * 16)
__global__ void chunksum_kernel(const float* __restrict__ V) {
    extern __shared__ float4 sm4[];
    float4* kp4 = sm4;            // 64 x 33
    float4* v4  = kp4 + 64 * 33;  // 64 x 17
    float* kpf = reinterpret_cast<float*>(kp4);  // row stride 132 floats

    int bid = blockIdx.x;
    int bh = bid / NCq, c = bid % NCq;
    int b = bh / Hq, h = bh % Hq;
    int tid = threadIdx.x;
    int lbase = c * Cq;

    for (int i = tid; i < 64 * 32; i += 256) {
        int l = i >> 5, m4 = i & 31;
        kp4[l * 33 + m4] = reinterpret_cast<const float4*>(g_kp)[(bh * Lq + lbase + l) * 32 + m4];
    }
    for (int i = tid; i < 64 * 16; i += 256) {
        int l = i >> 4, d4 = i & 15;
        v4[l * 17 + d4] = reinterpret_cast<const float4*>(V)[((b * Lq + lbase + l) * Hq + h) * 16 + d4];
    }
    __syncthreads();

    int d4    = tid & 15;
    int mbase = (tid >> 4) * 8;
    float4 acc[8];
#pragma unroll
    for (int j = 0; j < 8; j++) acc[j] = f4z();

    for (int l = 0; l < 64; l++) {
        float4 vv = v4[l * 17 + d4];
#pragma unroll
        for (int j = 0; j < 8; j++) {
            float kk = kpf[l * 132 + mbase + j];
            fma41(acc[j], kk, vv);
        }
    }
    int base = (bh * NCq + c) * Mq;
#pragma unroll
    for (int j = 0; j < 8; j++)
        reinterpret_cast<float4*>(g_kv)[(base + mbase + j) * 16 + d4] = acc[j];

    if (tid < 128) {
        float s = 0.f;
        for (int l = 0; l < 64; l++) s += kpf[l * 132 + tid];
        g_ks[base + tid] = s;
    }
}

// ======================= Kernel 3: exclusive prefix over chunks ==============
// grid BH*8 (8 slices per bh), 256 threads; each thread owns 1 float4
__global__ void scan_kernel() {
    int bh    = blockIdx.x >> 3;
    int slice = blockIdx.x & 7;
    int tid   = threadIdx.x;
    int base4 = slice * 256 + tid;          // per-(bh,c) = 2048 float4
    float4* kv4 = reinterpret_cast<float4*>(g_kv);

    float4 p = f4z();
#pragma unroll 2
    for (int c = 0; c < NCq; c++) {
        int idx = (bh * NCq + c) * 2048 + base4;
        float4 a = kv4[idx];
        kv4[idx] = p;
        add4(p, a);
    }

    if (slice == 0 && tid < 128) {
        float pk = 0.f;
        for (int c = 0; c < NCq; c += 4) {
            int i0 = (bh * NCq + c) * Mq + tid;
            float a0 = g_ks[i0], a1 = g_ks[i0 + Mq], a2 = g_ks[i0 + 2 * Mq], a3 = g_ks[i0 + 3 * Mq];
            g_ks[i0]          = pk;
            g_ks[i0 + Mq]     = pk + a0;
            g_ks[i0 + 2 * Mq] = pk + a0 + a1;
            g_ks[i0 + 3 * Mq] = pk + a0 + a1 + a2;
            pk += a0 + a1 + a2 + a3;
        }
    }
}

// ======================= Kernel 4: per-chunk output (TF32 MMA) ==============
// grid BH*NC, 256 threads (8 warps).
// smem (u32):
//   qp_s [64][132] tf32  (A, k=m)        8448
//   kp_s [64][132] tf32  (B for S: [n=l'][k=m])  8448
//   kvT  [64][132] tf32  (B for qp@KV: [n=d][k=m]) 8448
//   vT   [64][68]  tf32  (B for S@v: [n=d][k=l'])  4352
//   Sf   [64][68]  tf32-as-float (A for S@v; masked) 4352
//   ks[128], den[64]
#define OUT_SMEM ((8448 * 3 + 4352 * 2 + 192) * 4)
__global__ void out_kernel(const float* __restrict__ V, float* __restrict__ OUT) {
    extern __shared__ uint32_t sm[];
    uint32_t* qp_s = sm;                 // [64][132]
    uint32_t* kp_s = qp_s + 8448;        // [64][132]
    uint32_t* kvT  = kp_s + 8448;        // [64][132]
    uint32_t* vT   = kvT + 8448;         // [64][68]
    uint32_t* Sfu  = vT + 4352;          // [64][68]
    float*    Sff  = reinterpret_cast<float*>(Sfu);
    float*    ks   = reinterpret_cast<float*>(Sfu + 4352);   // [128]
    float*    den  = ks + 128;                               // [64]

    int bid = blockIdx.x;
    int bh = bid / NCq, c = bid % NCq;
    int b = bh / Hq, h = bh % Hq;
    int tid = threadIdx.x;
    int lbase = c * Cq;

    // ---- fills ----
    for (int i = tid; i < 64 * 32; i += 256) {
        int l = i >> 5, m4 = i & 31;
        float4 q = reinterpret_cast<const float4*>(g_qp)[(bh * Lq + lbase + l) * 32 + m4];
        float4 k = reinterpret_cast<const float4*>(g_kp)[(bh * Lq + lbase + l) * 32 + m4];
        *reinterpret_cast<uint4*>(&qp_s[l * 132 + m4 * 4]) = cvt4(q);
        *reinterpret_cast<uint4*>(&kp_s[l * 132 + m4 * 4]) = cvt4(k);
    }
    for (int i = tid; i < 64 * 16; i += 256) {
        int l = i >> 4, d4 = i & 15;
        float4 v = reinterpret_cast<const float4*>(V)[((b * Lq + lbase + l) * Hq + h) * 16 + d4];
        vT[(d4 * 4 + 0) * 68 + l] = f2tf(v.x);
        vT[(d4 * 4 + 1) * 68 + l] = f2tf(v.y);
        vT[(d4 * 4 + 2) * 68 + l] = f2tf(v.z);
        vT[(d4 * 4 + 3) * 68 + l] = f2tf(v.w);
    }
    for (int i = tid; i < 128 * 16; i += 256) {
        int m = i >> 4, d4 = i & 15;
        float4 v = reinterpret_cast<const float4*>(g_kv)[((bh * NCq + c) * Mq + m) * 16 + d4];
        kvT[(d4 * 4 + 0) * 132 + m] = f2tf(v.x);
        kvT[(d4 * 4 + 1) * 132 + m] = f2tf(v.y);
        kvT[(d4 * 4 + 2) * 132 + m] = f2tf(v.z);
        kvT[(d4 * 4 + 3) * 132 + m] = f2tf(v.w);
    }
    if (tid < 128) ks[tid] = g_ks[(bh * NCq + c) * Mq + tid];
    __syncthreads();

    int wid = tid >> 5, lane = tid & 31;
    int g = lane >> 2, t = lane & 3;
    int mt = wid & 3;     // rows [16*mt, +16)
    int np = wid >> 2;    // cols [32*np, +32)
    int r0 = mt * 16 + g, r1 = r0 + 8;
    int ar0 = r0 * 132, ar1 = r1 * 132;

    // ---- S = qp @ kp^T (K=128), causal-masked, tf32-rounded into Sf ----
    {
        float sacc[4][4];
#pragma unroll
        for (int j = 0; j < 4; j++) sacc[j][0] = sacc[j][1] = sacc[j][2] = sacc[j][3] = 0.f;
#pragma unroll
        for (int k0 = 0; k0 < 128; k0 += 8) {
            uint32_t a0 = qp_s[ar0 + k0 + t];
            uint32_t a1 = qp_s[ar1 + k0 + t];
            uint32_t a2 = qp_s[ar0 + k0 + t + 4];
            uint32_t a3 = qp_s[ar1 + k0 + t + 4];
#pragma unroll
            for (int j = 0; j < 4; j++) {
                int n = np * 32 + j * 8 + g;
                mma8(sacc[j], a0, a1, a2, a3, kp_s[n * 132 + k0 + t], kp_s[n * 132 + k0 + t + 4]);
            }
        }
#pragma unroll
        for (int j = 0; j < 4; j++) {
            int cb = np * 32 + j * 8 + 2 * t;
            uint2 w0, w1;
            w0.x = (r0 >= cb)     ? f2tf(sacc[j][0]) : 0u;
            w0.y = (r0 >= cb + 1) ? f2tf(sacc[j][1]) : 0u;
            w1.x = (r1 >= cb)     ? f2tf(sacc[j][2]) : 0u;
            w1.y = (r1 >= cb + 1) ? f2tf(sacc[j][3]) : 0u;
            *reinterpret_cast<uint2*>(&Sfu[r0 * 68 + cb]) = w0;
            *reinterpret_cast<uint2*>(&Sfu[r1 * 68 + cb]) = w1;
        }
    }
    __syncthreads();

    // ---- denominator: row-sum(S) + qp . ksum_prefix (4 lanes per row) ----
    {
        int l = tid >> 2, q4 = tid & 3;
        const float* qpf = reinterpret_cast<const float*>(qp_s);
        float s = 0.f;
        for (int lp = q4; lp < 64; lp += 4) s += Sff[l * 68 + lp];
        for (int m = q4; m < Mq; m += 4)   s = fmaf(qpf[l * 132 + m], ks[m], s);
        s += __shfl_xor_sync(0xffffffffu, s, 2);
        s += __shfl_xor_sync(0xffffffffu, s, 1);
        if (q4 == 0) den[l] = s;
    }
    __syncthreads();

    // ---- num = S @ v (K=64, upper tri of S is zero) + qp @ KV (K=128) ----
    float nacc[4][4];
#pragma unroll
    for (int j = 0; j < 4; j++) nacc[j][0] = nacc[j][1] = nacc[j][2] = nacc[j][3] = 0.f;

    int sr0 = r0 * 68, sr1 = r1 * 68;
#pragma unroll
    for (int k0 = 0; k0 < 64; k0 += 8) {
        uint32_t a0 = Sfu[sr0 + k0 + t];
        uint32_t a1 = Sfu[sr1 + k0 + t];
        uint32_t a2 = Sfu[sr0 + k0 + t + 4];
        uint32_t a3 = Sfu[sr1 + k0 + t + 4];
#pragma unroll
        for (int j = 0; j < 4; j++) {
            int n = np * 32 + j * 8 + g;
            mma8(nacc[j], a0, a1, a2, a3, vT[n * 68 + k0 + t], vT[n * 68 + k0 + t + 4]);
        }
    }
#pragma unroll
    for (int k0 = 0; k0 < 128; k0 += 8) {
        uint32_t a0 = qp_s[ar0 + k0 + t];
        uint32_t a1 = qp_s[ar1 + k0 + t];
        uint32_t a2 = qp_s[ar0 + k0 + t + 4];
        uint32_t a3 = qp_s[ar1 + k0 + t + 4];
#pragma unroll
        for (int j = 0; j < 4; j++) {
            int n = np * 32 + j * 8 + g;
            mma8(nacc[j], a0, a1, a2, a3, kvT[n * 132 + k0 + t], kvT[n * 132 + k0 + t + 4]);
        }
    }

    // ---- divide by den, store ----
    float i0 = 1.0f / den[r0];
    float i1 = 1.0f / den[r1];
    int ob = (b * Lq + lbase) * Hq + h;
#pragma unroll
    for (int j = 0; j < 4; j++) {
        int d = np * 32 + j * 8 + 2 * t;
        float2 w0, w1;
        w0.x = nacc[j][0] * i0; w0.y = nacc[j][1] * i0;
        w1.x = nacc[j][2] * i1; w1.y = nacc[j][3] * i1;
        reinterpret_cast<float2*>(OUT)[((ob + r0 * Hq) * Dq + d) >> 1] = w0;
        reinterpret_cast<float2*>(OUT)[((ob + r1 * Hq) * Dq + d) >> 1] = w1;
    }
}

// ============================ launch ============================
extern "C" void kernel_launch(void* const* d_in, const int* in_sizes, int n_in,
                              void* d_out, int out_size) {
    (void)in_sizes; (void)n_in; (void)out_size;
    const float* Q = (const float*)d_in[0];
    const float* K = (const float*)d_in[1];
    const float* V = (const float*)d_in[2];
    const float* P = (const float*)d_in[3];
    float* OUT = (float*)d_out;

    cudaFuncSetAttribute(proj_kernel,     cudaFuncAttributeMaxDynamicSharedMemorySize, PROJ_SMEM);
    cudaFuncSetAttribute(chunksum_kernel, cudaFuncAttributeMaxDynamicSharedMemorySize, CS_SMEM);
    cudaFuncSetAttribute(out_kernel,      cudaFuncAttributeMaxDynamicSharedMemorySize, OUT_SMEM);

    proj_kernel<<<2 * BHq * NCq, 256, PROJ_SMEM>>>(Q, K, P);
    chunksum_kernel<<<BHq * NCq, 256, CS_SMEM>>>(V);
    scan_kernel<<<BHq * 8, 256>>>();
    out_kernel<<<BHq * NCq, 256, OUT_SMEM>>>(V, OUT);
}

// round 6
// speedup vs baseline: 2.1433x; 1.4280x over previous
#include <cuda_runtime.h>
#include <stdint.h>
#include <math.h>

// Problem constants (fixed by setup_inputs)
#define Bq 2
#define Lq 4096
#define Hq 8
#define Dq 64
#define Mq 128
#define Cq 64
#define NCq (Lq / Cq)      // 64 chunks
#define BHq (Bq * Hq)      // 16 sequences

#define RATIO 0.08838834764831845f   // 1/sqrt(128)
#define STAB  1e-3f

// ---------------- scratch (device globals; no runtime allocation) ----------
__device__ float g_kv[BHq * NCq * Mq * Dq];    // [bh, c, m, d] -> exclusive prefix
__device__ float g_ks[BHq * NCq * Mq];         // [bh, c, m]   -> exclusive prefix

// ---------------- helpers ----------------
__device__ __forceinline__ float4 f4z() { return make_float4(0.f, 0.f, 0.f, 0.f); }
__device__ __forceinline__ void add4(float4& a, float4 b) {
    a.x += b.x; a.y += b.y; a.z += b.z; a.w += b.w;
}
__device__ __forceinline__ uint32_t f2tf(float x) {
    uint32_t r; asm("cvt.rna.tf32.f32 %0, %1;" : "=r"(r) : "f"(x)); return r;
}
__device__ __forceinline__ uint4 cvt4(float4 v) {
    return make_uint4(f2tf(v.x), f2tf(v.y), f2tf(v.z), f2tf(v.w));
}
// m16n8k8 tf32 mma, fp32 accumulate (D = A*B + D)
__device__ __forceinline__ void mma8(float* c, uint32_t a0, uint32_t a1, uint32_t a2, uint32_t a3,
                                     uint32_t b0, uint32_t b1) {
    asm("mma.sync.aligned.m16n8k8.row.col.f32.tf32.tf32.f32 "
        "{%0,%1,%2,%3},{%4,%5,%6,%7},{%8,%9},{%0,%1,%2,%3};"
        : "+f"(c[0]), "+f"(c[1]), "+f"(c[2]), "+f"(c[3])
        : "r"(a0), "r"(a1), "r"(a2), "r"(a3), "r"(b0), "r"(b1));
}
__device__ __forceinline__ float relu_s(float x) { return fmaxf(x * RATIO, 0.f) + STAB; }

// ======================= Kernel 1: chunk kp -> KV / ksum ====================
// grid BH*NC, 256 threads (8 warps).
// smem u32: Xk [64][68] | Ps [128][68] | kpT [128][68] | vT [64][68]
#define CKV_SMEM ((4352 + 8704 + 8704 + 4352) * 4)
__global__ void __launch_bounds__(256, 2) chunkkv_kernel(
        const float* __restrict__ K, const float* __restrict__ V,
        const float* __restrict__ P) {
    extern __shared__ uint32_t sm[];
    uint32_t* Xk  = sm;                 // [64][68]
    uint32_t* Ps  = Xk + 4352;          // [128][68]
    uint32_t* kpT = Ps + 8704;          // [128][68]  (kp transposed: [m][l])
    uint32_t* vT  = kpT + 8704;         // [64][68]   ([d][l])

    int bid = blockIdx.x;
    int bh = bid / NCq, c = bid % NCq;
    int b = bh / Hq, h = bh % Hq;
    int tid = threadIdx.x;
    int lbase = c * Cq;

    for (int i = tid; i < 128 * 16; i += 256) {
        int m = i >> 4, d4 = i & 15;
        float4 v = reinterpret_cast<const float4*>(P)[m * 16 + d4];
        *reinterpret_cast<uint4*>(&Ps[m * 68 + d4 * 4]) = cvt4(v);
    }
    for (int i = tid; i < 64 * 16; i += 256) {
        int l = i >> 4, d4 = i & 15;
        float4 v = reinterpret_cast<const float4*>(K)[((b * Lq + lbase + l) * Hq + h) * 16 + d4];
        *reinterpret_cast<uint4*>(&Xk[l * 68 + d4 * 4]) = cvt4(v);
        float4 vv = reinterpret_cast<const float4*>(V)[((b * Lq + lbase + l) * Hq + h) * 16 + d4];
        vT[(d4 * 4 + 0) * 68 + l] = f2tf(vv.x);
        vT[(d4 * 4 + 1) * 68 + l] = f2tf(vv.y);
        vT[(d4 * 4 + 2) * 68 + l] = f2tf(vv.z);
        vT[(d4 * 4 + 3) * 68 + l] = f2tf(vv.w);
    }
    __syncthreads();

    int wid = tid >> 5, lane = tid & 31;
    int g = lane >> 2, t = lane & 3;

    // ---- kp = relu(Xk @ P^T), stored transposed into kpT [m][l] ----
    {
        int mt = wid & 3, nh = wid >> 2;
        int l0 = mt * 16 + g, l1 = l0 + 8;
        int ar0 = l0 * 68, ar1 = l1 * 68;
        float acc[8][4];
#pragma unroll
        for (int j = 0; j < 8; j++) acc[j][0] = acc[j][1] = acc[j][2] = acc[j][3] = 0.f;
#pragma unroll
        for (int k0 = 0; k0 < 64; k0 += 8) {
            uint32_t a0 = Xk[ar0 + k0 + t];
            uint32_t a1 = Xk[ar1 + k0 + t];
            uint32_t a2 = Xk[ar0 + k0 + t + 4];
            uint32_t a3 = Xk[ar1 + k0 + t + 4];
#pragma unroll
            for (int j = 0; j < 8; j++) {
                int n = nh * 64 + j * 8 + g;
                mma8(acc[j], a0, a1, a2, a3, Ps[n * 68 + k0 + t], Ps[n * 68 + k0 + t + 4]);
            }
        }
#pragma unroll
        for (int j = 0; j < 8; j++) {
            int col = nh * 64 + j * 8 + 2 * t;
            kpT[col * 68 + l0]       = f2tf(relu_s(acc[j][0]));
            kpT[(col + 1) * 68 + l0] = f2tf(relu_s(acc[j][1]));
            kpT[col * 68 + l1]       = f2tf(relu_s(acc[j][2]));
            kpT[(col + 1) * 68 + l1] = f2tf(relu_s(acc[j][3]));
        }
    }
    __syncthreads();

    int cbase = (bh * NCq + c) * Mq;

    // ---- ksum[m] = sum_l kp[l][m] (tf32 bits are valid fp32) ----
    {
        int m = tid >> 1, half = tid & 1;
        const float* kf = reinterpret_cast<const float*>(kpT);
        float s = 0.f;
        for (int l = 0; l < 32; l++) s += kf[m * 68 + half * 32 + l];
        s += __shfl_xor_sync(0xffffffffu, s, 1);
        if (half == 0) g_ks[cbase + m] = s;
    }

    // ---- KV = kp^T @ v : A = kpT [m][l], B = vT [d][l], K=64 ----
    {
        int m0 = wid * 16 + g, m1 = m0 + 8;
        int ar0 = m0 * 68, ar1 = m1 * 68;
        float acc[8][4];
#pragma unroll
        for (int j = 0; j < 8; j++) acc[j][0] = acc[j][1] = acc[j][2] = acc[j][3] = 0.f;
#pragma unroll
        for (int k0 = 0; k0 < 64; k0 += 8) {
            uint32_t a0 = kpT[ar0 + k0 + t];
            uint32_t a1 = kpT[ar1 + k0 + t];
            uint32_t a2 = kpT[ar0 + k0 + t + 4];
            uint32_t a3 = kpT[ar1 + k0 + t + 4];
#pragma unroll
            for (int j = 0; j < 8; j++) {
                int n = j * 8 + g;
                mma8(acc[j], a0, a1, a2, a3, vT[n * 68 + k0 + t], vT[n * 68 + k0 + t + 4]);
            }
        }
#pragma unroll
        for (int j = 0; j < 8; j++) {
            int d = j * 8 + 2 * t;
            float2 w0 = make_float2(acc[j][0], acc[j][1]);
            float2 w1 = make_float2(acc[j][2], acc[j][3]);
            reinterpret_cast<float2*>(g_kv)[((cbase + m0) * Dq + d) >> 1] = w0;
            reinterpret_cast<float2*>(g_kv)[((cbase + m1) * Dq + d) >> 1] = w1;
        }
    }
}

// ======================= Kernel 2: exclusive prefix over chunks ==============
// grid BH*8 (8 slices per bh), 256 threads; each thread owns 1 float4
__global__ void scan_kernel() {
    int bh    = blockIdx.x >> 3;
    int slice = blockIdx.x & 7;
    int tid   = threadIdx.x;
    int base4 = slice * 256 + tid;          // per-(bh,c) = 2048 float4
    float4* kv4 = reinterpret_cast<float4*>(g_kv);

    float4 p = f4z();
#pragma unroll 2
    for (int c = 0; c < NCq; c++) {
        int idx = (bh * NCq + c) * 2048 + base4;
        float4 a = kv4[idx];
        kv4[idx] = p;
        add4(p, a);
    }

    if (slice == 0 && tid < 128) {
        float pk = 0.f;
        for (int c = 0; c < NCq; c += 4) {
            int i0 = (bh * NCq + c) * Mq + tid;
            float a0 = g_ks[i0], a1 = g_ks[i0 + Mq], a2 = g_ks[i0 + 2 * Mq], a3 = g_ks[i0 + 3 * Mq];
            g_ks[i0]          = pk;
            g_ks[i0 + Mq]     = pk + a0;
            g_ks[i0 + 2 * Mq] = pk + a0 + a1;
            g_ks[i0 + 3 * Mq] = pk + a0 + a1 + a2;
            pk += a0 + a1 + a2 + a3;
        }
    }
}

// ======================= Kernel 3: fused proj + output ======================
// grid BH*NC, 512 threads (16 warps).
// smem u32 layout:
//   Xq [64][68] (-> reused as Sf) | Xk [64][68] | Ps [128][68] (-> kvT [64][132])
//   qp_s [64][132] | kp_s [64][132] | vT [64][68] | ks[128]f | den[64]f
#define OUT_SMEM ((4352 + 4352 + 8704 + 8448 + 8448 + 4352 + 192) * 4)
__global__ void __launch_bounds__(512, 1) out_kernel(
        const float* __restrict__ Q, const float* __restrict__ K,
        const float* __restrict__ V, const float* __restrict__ P,
        float* __restrict__ OUT) {
    extern __shared__ uint32_t sm[];
    uint32_t* Xq   = sm;               // [64][68] -> Sf after proj phase
    uint32_t* Xk   = Xq + 4352;        // [64][68]
    uint32_t* Ps   = Xk + 4352;        // [128][68] -> kvT [64][132] after proj
    uint32_t* qp_s = Ps + 8704;        // [64][132]
    uint32_t* kp_s = qp_s + 8448;      // [64][132]
    uint32_t* vT   = kp_s + 8448;      // [64][68]
    float*    ks   = reinterpret_cast<float*>(vT + 4352);  // [128]
    float*    den  = ks + 128;                              // [64]
    uint32_t* Sfu  = Xq;               // alias
    uint32_t* kvT  = Ps;               // alias [64][132] ([d][m])
    float*    Sff  = reinterpret_cast<float*>(Sfu);

    int bid = blockIdx.x;
    int bh = bid / NCq, c = bid % NCq;
    int b = bh / Hq, h = bh % Hq;
    int tid = threadIdx.x;
    int lbase = c * Cq;

    // ---- phase 0: fills ----
    for (int i = tid; i < 128 * 16; i += 512) {
        int m = i >> 4, d4 = i & 15;
        float4 v = reinterpret_cast<const float4*>(P)[m * 16 + d4];
        *reinterpret_cast<uint4*>(&Ps[m * 68 + d4 * 4]) = cvt4(v);
    }
    for (int i = tid; i < 64 * 16; i += 512) {
        int l = i >> 4, d4 = i & 15;
        int gidx = ((b * Lq + lbase + l) * Hq + h) * 16 + d4;
        float4 q = reinterpret_cast<const float4*>(Q)[gidx];
        float4 k = reinterpret_cast<const float4*>(K)[gidx];
        *reinterpret_cast<uint4*>(&Xq[l * 68 + d4 * 4]) = cvt4(q);
        *reinterpret_cast<uint4*>(&Xk[l * 68 + d4 * 4]) = cvt4(k);
        float4 vv = reinterpret_cast<const float4*>(V)[gidx];
        vT[(d4 * 4 + 0) * 68 + l] = f2tf(vv.x);
        vT[(d4 * 4 + 1) * 68 + l] = f2tf(vv.y);
        vT[(d4 * 4 + 2) * 68 + l] = f2tf(vv.z);
        vT[(d4 * 4 + 3) * 68 + l] = f2tf(vv.w);
    }
    if (tid < 128) ks[tid] = g_ks[(bh * NCq + c) * Mq + tid];
    __syncthreads();

    int wid = tid >> 5, lane = tid & 31;
    int g = lane >> 2, t = lane & 3;

    // ---- phase 1: qp/kp = relu(X @ P^T) via MMA; warps 0-7 qp, 8-15 kp ----
    {
        int pw = wid & 7, which = wid >> 3;
        uint32_t* src = which ? Xk : Xq;
        uint32_t* dst = which ? kp_s : qp_s;
        int mt = pw & 3, nh = pw >> 2;
        int r0 = mt * 16 + g, r1 = r0 + 8;
        int ar0 = r0 * 68, ar1 = r1 * 68;
        float acc[8][4];
#pragma unroll
        for (int j = 0; j < 8; j++) acc[j][0] = acc[j][1] = acc[j][2] = acc[j][3] = 0.f;
#pragma unroll
        for (int k0 = 0; k0 < 64; k0 += 8) {
            uint32_t a0 = src[ar0 + k0 + t];
            uint32_t a1 = src[ar1 + k0 + t];
            uint32_t a2 = src[ar0 + k0 + t + 4];
            uint32_t a3 = src[ar1 + k0 + t + 4];
#pragma unroll
            for (int j = 0; j < 8; j++) {
                int n = nh * 64 + j * 8 + g;
                mma8(acc[j], a0, a1, a2, a3, Ps[n * 68 + k0 + t], Ps[n * 68 + k0 + t + 4]);
            }
        }
#pragma unroll
        for (int j = 0; j < 8; j++) {
            int col = nh * 64 + j * 8 + 2 * t;
            uint2 w0 = make_uint2(f2tf(relu_s(acc[j][0])), f2tf(relu_s(acc[j][1])));
            uint2 w1 = make_uint2(f2tf(relu_s(acc[j][2])), f2tf(relu_s(acc[j][3])));
            *reinterpret_cast<uint2*>(&dst[r0 * 132 + col]) = w0;
            *reinterpret_cast<uint2*>(&dst[r1 * 132 + col]) = w1;
        }
    }
    __syncthreads();

    int mt = wid & 3, nt = wid >> 2;
    int r0 = mt * 16 + g, r1 = r0 + 8;
    int qr0 = r0 * 132, qr1 = r1 * 132;

    // ---- phase 2: issue kv loads; S = qp @ kp^T masked -> Sf; stash kvT ----
    float4 kvreg[4];
#pragma unroll
    for (int kk = 0; kk < 4; kk++) {
        int i = tid + kk * 512;                 // 2048 float4 = 128m x 16(d4)
        int m = i >> 4, d4 = i & 15;
        kvreg[kk] = reinterpret_cast<const float4*>(g_kv)[((bh * NCq + c) * Mq + m) * 16 + d4];
    }
    {
        float sacc[2][4];
#pragma unroll
        for (int j = 0; j < 2; j++) sacc[j][0] = sacc[j][1] = sacc[j][2] = sacc[j][3] = 0.f;
#pragma unroll
        for (int k0 = 0; k0 < 128; k0 += 8) {
            uint32_t a0 = qp_s[qr0 + k0 + t];
            uint32_t a1 = qp_s[qr1 + k0 + t];
            uint32_t a2 = qp_s[qr0 + k0 + t + 4];
            uint32_t a3 = qp_s[qr1 + k0 + t + 4];
#pragma unroll
            for (int j = 0; j < 2; j++) {
                int n = nt * 16 + j * 8 + g;
                mma8(sacc[j], a0, a1, a2, a3, kp_s[n * 132 + k0 + t], kp_s[n * 132 + k0 + t + 4]);
            }
        }
#pragma unroll
        for (int j = 0; j < 2; j++) {
            int cb = nt * 16 + j * 8 + 2 * t;
            uint2 w0, w1;
            w0.x = (r0 >= cb)     ? f2tf(sacc[j][0]) : 0u;
            w0.y = (r0 >= cb + 1) ? f2tf(sacc[j][1]) : 0u;
            w1.x = (r1 >= cb)     ? f2tf(sacc[j][2]) : 0u;
            w1.y = (r1 >= cb + 1) ? f2tf(sacc[j][3]) : 0u;
            *reinterpret_cast<uint2*>(&Sfu[r0 * 68 + cb]) = w0;
            *reinterpret_cast<uint2*>(&Sfu[r1 * 68 + cb]) = w1;
        }
    }
    // stash kv transposed into kvT [d][m] (Ps region; free after proj sync)
#pragma unroll
    for (int kk = 0; kk < 4; kk++) {
        int i = tid + kk * 512;
        int m = i >> 4, d4 = i & 15;
        kvT[(d4 * 4 + 0) * 132 + m] = f2tf(kvreg[kk].x);
        kvT[(d4 * 4 + 1) * 132 + m] = f2tf(kvreg[kk].y);
        kvT[(d4 * 4 + 2) * 132 + m] = f2tf(kvreg[kk].z);
        kvT[(d4 * 4 + 3) * 132 + m] = f2tf(kvreg[kk].w);
    }
    __syncthreads();

    // ---- phase 3: denominator (8 lanes per row) ----
    {
        int l = tid >> 3, q8 = tid & 7;
        const float* qpf = reinterpret_cast<const float*>(qp_s);
        float s = 0.f;
        for (int lp = q8; lp < 64; lp += 8) s += Sff[l * 68 + lp];
        for (int m = q8; m < Mq; m += 8)   s = fmaf(qpf[l * 132 + m], ks[m], s);
        s += __shfl_xor_sync(0xffffffffu, s, 4);
        s += __shfl_xor_sync(0xffffffffu, s, 2);
        s += __shfl_xor_sync(0xffffffffu, s, 1);
        if (q8 == 0) den[l] = s;
    }
    __syncthreads();

    // ---- phase 4: num = S @ v (K=64) + qp @ KV (K=128); divide; store ----
    float nacc[2][4];
#pragma unroll
    for (int j = 0; j < 2; j++) nacc[j][0] = nacc[j][1] = nacc[j][2] = nacc[j][3] = 0.f;

    int sr0 = r0 * 68, sr1 = r1 * 68;
#pragma unroll
    for (int k0 = 0; k0 < 64; k0 += 8) {
        uint32_t a0 = Sfu[sr0 + k0 + t];
        uint32_t a1 = Sfu[sr1 + k0 + t];
        uint32_t a2 = Sfu[sr0 + k0 + t + 4];
        uint32_t a3 = Sfu[sr1 + k0 + t + 4];
#pragma unroll
        for (int j = 0; j < 2; j++) {
            int n = nt * 16 + j * 8 + g;
            mma8(nacc[j], a0, a1, a2, a3, vT[n * 68 + k0 + t], vT[n * 68 + k0 + t + 4]);
        }
    }
#pragma unroll
    for (int k0 = 0; k0 < 128; k0 += 8) {
        uint32_t a0 = qp_s[qr0 + k0 + t];
        uint32_t a1 = qp_s[qr1 + k0 + t];
        uint32_t a2 = qp_s[qr0 + k0 + t + 4];
        uint32_t a3 = qp_s[qr1 + k0 + t + 4];
#pragma unroll
        for (int j = 0; j < 2; j++) {
            int n = nt * 16 + j * 8 + g;
            mma8(nacc[j], a0, a1, a2, a3, kvT[n * 132 + k0 + t], kvT[n * 132 + k0 + t + 4]);
        }
    }

    float i0 = 1.0f / den[r0];
    float i1 = 1.0f / den[r1];
    int ob = (b * Lq + lbase) * Hq + h;
#pragma unroll
    for (int j = 0; j < 2; j++) {
        int d = nt * 16 + j * 8 + 2 * t;
        float2 w0 = make_float2(nacc[j][0] * i0, nacc[j][1] * i0);
        float2 w1 = make_float2(nacc[j][2] * i1, nacc[j][3] * i1);
        reinterpret_cast<float2*>(OUT)[((ob + r0 * Hq) * Dq + d) >> 1] = w0;
        reinterpret_cast<float2*>(OUT)[((ob + r1 * Hq) * Dq + d) >> 1] = w1;
    }
}

// ============================ launch ============================
extern "C" void kernel_launch(void* const* d_in, const int* in_sizes, int n_in,
                              void* d_out, int out_size) {
    (void)in_sizes; (void)n_in; (void)out_size;
    const float* Q = (const float*)d_in[0];
    const float* K = (const float*)d_in[1];
    const float* V = (const float*)d_in[2];
    const float* P = (const float*)d_in[3];
    float* OUT = (float*)d_out;

    cudaFuncSetAttribute(chunkkv_kernel, cudaFuncAttributeMaxDynamicSharedMemorySize, CKV_SMEM);
    cudaFuncSetAttribute(out_kernel,     cudaFuncAttributeMaxDynamicSharedMemorySize, OUT_SMEM);

    chunkkv_kernel<<<BHq * NCq, 256, CKV_SMEM>>>(K, V, P);
    scan_kernel<<<BHq * 8, 256>>>();
    out_kernel<<<BHq * NCq, 512, OUT_SMEM>>>(Q, K, V, P, OUT);
}